// round 9
// baseline (speedup 1.0000x reference)
#include <cuda_runtime.h>
#include <cuda_fp16.h>
#include <cstdint>

#define NUM_NODES 100000
#define NUM_EDGES 50000
#define NUM_CONN  800000
#define IN_DIM    256
#define HIDDEN    128
#define OUT_DIM   17
#define LN_EPS    1e-5f

// ---------------- scratch (static device globals; no allocation) ----------------
__device__ int g_counts[NUM_EDGES];
__device__ int g_offsets[NUM_EDGES + 1];
__device__ int g_cursor[NUM_EDGES];
__device__ int g_csr[NUM_CONN];
__device__ __align__(16) __half g_nf_h[(size_t)NUM_NODES * IN_DIM];  // 51.2 MB fp16 mirror

// ---------------- packed f32x2 helpers ----------------
__device__ __forceinline__ void fma_f32x2(unsigned long long& d,
                                          unsigned long long a,
                                          unsigned long long b) {
    asm("fma.rn.f32x2 %0, %1, %2, %0;" : "+l"(d) : "l"(a), "l"(b));
}
__device__ __forceinline__ unsigned long long pack_f32x2(float lo, float hi) {
    unsigned long long r;
    asm("mov.b64 %0, {%1, %2};" : "=l"(r) : "f"(lo), "f"(hi));
    return r;
}
__device__ __forceinline__ float2 unpack_f32x2(unsigned long long v) {
    float2 r;
    asm("mov.b64 {%0, %1}, %2;" : "=f"(r.x), "=f"(r.y) : "l"(v));
    return r;
}

// ---------------- K-1: convert node_features fp32 -> fp16 mirror ----------------
// Each thread converts 8 elements (two float4 reads -> one 16B half8 write).
__global__ void convert_kernel(const float* __restrict__ nf) {
    size_t i = (size_t)blockIdx.x * blockDim.x + threadIdx.x;
    size_t n8 = (size_t)NUM_NODES * IN_DIM / 8;
    if (i >= n8) return;
    const float4* src = (const float4*)nf;
    float4 f0 = __ldg(&src[i * 2]);
    float4 f1 = __ldg(&src[i * 2 + 1]);
    __half2 h[4];
    h[0] = __floats2half2_rn(f0.x, f0.y);
    h[1] = __floats2half2_rn(f0.z, f0.w);
    h[2] = __floats2half2_rn(f1.x, f1.y);
    h[3] = __floats2half2_rn(f1.z, f1.w);
    ((float4*)g_nf_h)[i] = *(float4*)h;
}

// ---------------- K0: zero counts ----------------
__global__ void zero_counts_kernel() {
    int i = blockIdx.x * blockDim.x + threadIdx.x;
    if (i < NUM_EDGES) g_counts[i] = 0;
}

// ---------------- K1: histogram of edge ids (hyperedge_index is int32) ----------------
__global__ void count_kernel(const int* __restrict__ he) {
    int c = blockIdx.x * blockDim.x + threadIdx.x;
    if (c < NUM_CONN) {
        int e = he[NUM_CONN + c];
        if ((unsigned)e < NUM_EDGES) atomicAdd(&g_counts[e], 1);
    }
}

// ---------------- K2: exclusive scan, smem-staged, coalesced ----------------
__global__ void __launch_bounds__(1024) scan_kernel() {
    extern __shared__ int sc[];               // NUM_EDGES ints = 200000 B
    const int PER = 49;
    __shared__ int wsum[32];
    int tid = threadIdx.x, lane = tid & 31, wid = tid >> 5;

    for (int i = tid; i < NUM_EDGES; i += 1024) sc[i] = g_counts[i];
    __syncthreads();

    int base = tid * PER;
    int s = 0;
    #pragma unroll
    for (int i = 0; i < PER; i++) {
        int idx = base + i;
        if (idx < NUM_EDGES) s += sc[idx];
    }
    int x = s;
    #pragma unroll
    for (int off = 1; off < 32; off <<= 1) {
        int t = __shfl_up_sync(0xffffffffu, x, off);
        if (lane >= off) x += t;
    }
    if (lane == 31) wsum[wid] = x;
    __syncthreads();
    if (wid == 0) {
        int t = wsum[lane];
        int y = t;
        #pragma unroll
        for (int off = 1; off < 32; off <<= 1) {
            int u = __shfl_up_sync(0xffffffffu, y, off);
            if (lane >= off) y += u;
        }
        wsum[lane] = y - t;
    }
    __syncthreads();
    int run = (x - s) + wsum[wid];
    #pragma unroll
    for (int i = 0; i < PER; i++) {
        int idx = base + i;
        if (idx < NUM_EDGES) {
            int c = sc[idx];
            sc[idx] = run;
            run += c;
        }
    }
    __syncthreads();
    for (int i = tid; i < NUM_EDGES; i += 1024) {
        int v = sc[i];
        g_offsets[i] = v;
        g_cursor[i]  = v;
    }
    if (tid == 1023) g_offsets[NUM_EDGES] = run;
}

// ---------------- K3: fill CSR ----------------
__global__ void fill_kernel(const int* __restrict__ he) {
    int c = blockIdx.x * blockDim.x + threadIdx.x;
    if (c < NUM_CONN) {
        int e = he[NUM_CONN + c];
        if ((unsigned)e < NUM_EDGES) {
            int pos = atomicAdd(&g_cursor[e], 1);
            int n = he[c];
            g_csr[pos] = ((unsigned)n < NUM_NODES) ? n : 0;
        }
    }
}

// ---------------- K4: FUSED fp16-gather-mean + GEMM1(FFMA2) + LN + ReLU + GEMM2 ----------------
// Block = 25 edges, 128 threads. Warp w gathers edges {w, w+4, ...}: each lane
// loads ONE 16-byte chunk (8 halves) per connection and accumulates in fp32.
#define ROWS 25
__global__ void __launch_bounds__(128) fused_mlp_kernel(
    const float* __restrict__ W1, const float* __restrict__ b1,
    const float* __restrict__ lng, const float* __restrict__ lnb,
    const float* __restrict__ W2, const float* __restrict__ b2,
    float* __restrict__ out)
{
    __shared__ float Xs[ROWS][IN_DIM];       // 25.6 KB
    __shared__ float Hs[ROWS][HIDDEN];       // 12.8 KB
    __shared__ float W2s[HIDDEN * OUT_DIM];  // 8.7 KB
    __shared__ float b2s[OUT_DIM];

    int tid  = threadIdx.x;
    int wid  = tid >> 5, lane = tid & 31;
    int row0 = blockIdx.x * ROWS;

    for (int idx = tid; idx < HIDDEN * OUT_DIM; idx += 128) W2s[idx] = W2[idx];
    if (tid < OUT_DIM) b2s[tid] = b2[tid];

    // ---- fp16 gather + fp32 mean into Xs: lane owns cols [8*lane, 8*lane+8) ----
    for (int r = wid; r < ROWS; r += 4) {
        int e   = row0 + r;
        int beg = g_offsets[e];
        int end = g_offsets[e + 1];
        float a[8];
        #pragma unroll
        for (int j = 0; j < 8; j++) a[j] = 0.f;

        int i = beg;
        for (; i + 2 <= end; i += 2) {
            int n0 = g_csr[i];
            int n1 = g_csr[i + 1];
            float4 q0 = __ldg((const float4*)(g_nf_h + (size_t)n0 * IN_DIM) + lane);
            float4 q1 = __ldg((const float4*)(g_nf_h + (size_t)n1 * IN_DIM) + lane);
            const __half2* h0 = (const __half2*)&q0;
            const __half2* h1 = (const __half2*)&q1;
            #pragma unroll
            for (int j = 0; j < 4; j++) {
                float2 f0 = __half22float2(h0[j]);
                float2 f1 = __half22float2(h1[j]);
                a[2 * j]     += f0.x + f1.x;
                a[2 * j + 1] += f0.y + f1.y;
            }
        }
        if (i < end) {
            int n = g_csr[i];
            float4 q = __ldg((const float4*)(g_nf_h + (size_t)n * IN_DIM) + lane);
            const __half2* h = (const __half2*)&q;
            #pragma unroll
            for (int j = 0; j < 4; j++) {
                float2 f = __half22float2(h[j]);
                a[2 * j]     += f.x;
                a[2 * j + 1] += f.y;
            }
        }
        int cnt = end - beg;
        float inv = 1.f / (float)(cnt > 0 ? cnt : 1);
        float4 o0 = make_float4(a[0] * inv, a[1] * inv, a[2] * inv, a[3] * inv);
        float4 o1 = make_float4(a[4] * inv, a[5] * inv, a[6] * inv, a[7] * inv);
        ((float4*)&Xs[r][0])[2 * lane]     = o0;
        ((float4*)&Xs[r][0])[2 * lane + 1] = o1;
    }
    __syncthreads();

    // ---- GEMM1, packed f32x2, software-pipelined W1 loads ----
    unsigned long long acc2[ROWS];
    #pragma unroll
    for (int r = 0; r < ROWS; r++) acc2[r] = 0ULL;

    float w0 = __ldg(&W1[0 * HIDDEN + tid]);
    float w1 = __ldg(&W1[1 * HIDDEN + tid]);
    float w2 = __ldg(&W1[2 * HIDDEN + tid]);
    float w3 = __ldg(&W1[3 * HIDDEN + tid]);

    #pragma unroll 2
    for (int k = 0; k < IN_DIM - 4; k += 4) {
        float n0 = __ldg(&W1[(k + 4) * HIDDEN + tid]);
        float n1 = __ldg(&W1[(k + 5) * HIDDEN + tid]);
        float n2 = __ldg(&W1[(k + 6) * HIDDEN + tid]);
        float n3 = __ldg(&W1[(k + 7) * HIDDEN + tid]);
        unsigned long long wA = pack_f32x2(w0, w1);
        unsigned long long wB = pack_f32x2(w2, w3);
        #pragma unroll
        for (int r = 0; r < ROWS; r++) {
            ulonglong2 xx = *(const ulonglong2*)&Xs[r][k];  // LDS.128 broadcast
            fma_f32x2(acc2[r], xx.x, wA);
            fma_f32x2(acc2[r], xx.y, wB);
        }
        w0 = n0; w1 = n1; w2 = n2; w3 = n3;
    }
    {   // last quad
        unsigned long long wA = pack_f32x2(w0, w1);
        unsigned long long wB = pack_f32x2(w2, w3);
        #pragma unroll
        for (int r = 0; r < ROWS; r++) {
            ulonglong2 xx = *(const ulonglong2*)&Xs[r][IN_DIM - 4];
            fma_f32x2(acc2[r], xx.x, wA);
            fma_f32x2(acc2[r], xx.y, wB);
        }
    }

    float b1v = b1[tid];
    #pragma unroll
    for (int r = 0; r < ROWS; r++) {
        float2 p = unpack_f32x2(acc2[r]);
        Hs[r][tid] = p.x + p.y + b1v;
    }
    __syncthreads();

    // ---- LayerNorm + ReLU, warp-per-row ----
    for (int r = wid; r < ROWS; r += 4) {
        float s = 0.f, s2 = 0.f;
        #pragma unroll
        for (int j = 0; j < 4; j++) {
            float v = Hs[r][lane + 32 * j];
            s += v; s2 += v * v;
        }
        #pragma unroll
        for (int o = 16; o; o >>= 1) {
            s  += __shfl_xor_sync(0xffffffffu, s, o);
            s2 += __shfl_xor_sync(0xffffffffu, s2, o);
        }
        float mu  = s * (1.f / HIDDEN);
        float var = s2 * (1.f / HIDDEN) - mu * mu;
        float rs  = rsqrtf(var + LN_EPS);
        #pragma unroll
        for (int j = 0; j < 4; j++) {
            int c = lane + 32 * j;
            float v = (Hs[r][c] - mu) * rs * lng[c] + lnb[c];
            Hs[r][c] = fmaxf(v, 0.f);
        }
    }
    __syncthreads();

    // ---- GEMM2 ----
    for (int idx = tid; idx < ROWS * OUT_DIM; idx += 128) {
        int r = idx / OUT_DIM, o = idx % OUT_DIM;
        float s = b2s[o];
        #pragma unroll 8
        for (int j = 0; j < HIDDEN; j++) s = fmaf(Hs[r][j], W2s[j * OUT_DIM + o], s);
        out[(size_t)(row0 + r) * OUT_DIM + o] = s;
    }
}

// ---------------- launch ----------------
extern "C" void kernel_launch(void* const* d_in, const int* in_sizes, int n_in,
                              void* d_out, int out_size)
{
    const float* node_features = (const float*)d_in[0];
    const int*   he            = (const int*)d_in[1];   // int32 (JAX x64 disabled)
    const float* W1            = (const float*)d_in[2];
    const float* b1            = (const float*)d_in[3];
    const float* ln_g          = (const float*)d_in[4];
    const float* ln_b          = (const float*)d_in[5];
    const float* W2            = (const float*)d_in[6];
    const float* b2            = (const float*)d_in[7];
    float*       out           = (float*)d_out;

    static const int SCAN_SMEM = NUM_EDGES * (int)sizeof(int);   // 200000 B
    cudaFuncSetAttribute(scan_kernel, cudaFuncAttributeMaxDynamicSharedMemorySize, SCAN_SMEM);

    const int n8 = NUM_NODES * IN_DIM / 8;
    convert_kernel<<<(n8 + 255) / 256, 256>>>(node_features);
    zero_counts_kernel<<<(NUM_EDGES + 255) / 256, 256>>>();
    count_kernel<<<(NUM_CONN + 255) / 256, 256>>>(he);
    scan_kernel<<<1, 1024, SCAN_SMEM>>>();
    fill_kernel<<<(NUM_CONN + 255) / 256, 256>>>(he);
    fused_mlp_kernel<<<NUM_EDGES / ROWS, 128>>>(W1, b1, ln_g, ln_b, W2, b2, out);
}

// round 10
// speedup vs baseline: 1.0607x; 1.0607x over previous
#include <cuda_runtime.h>
#include <cuda_bf16.h>
#include <cstdint>

#define NUM_NODES 100000
#define NUM_EDGES 50000
#define NUM_CONN  800000
#define IN_DIM    256
#define HIDDEN    128
#define OUT_DIM   17
#define LN_EPS    1e-5f

#define SCAN_BLK  256
#define SCAN_NBLK ((NUM_EDGES + SCAN_BLK - 1) / SCAN_BLK)   // 196

// ---------------- scratch (static device globals; no allocation) ----------------
__device__ int g_counts[NUM_EDGES];
__device__ int g_offsets[NUM_EDGES + 1];
__device__ int g_cursor[NUM_EDGES];
__device__ int g_csr[NUM_CONN];
__device__ int g_partials[SCAN_NBLK];

// ---------------- packed f32x2 helpers ----------------
__device__ __forceinline__ void fma_f32x2(unsigned long long& d,
                                          unsigned long long a,
                                          unsigned long long b) {
    asm("fma.rn.f32x2 %0, %1, %2, %0;" : "+l"(d) : "l"(a), "l"(b));
}
__device__ __forceinline__ unsigned long long pack_f32x2(float lo, float hi) {
    unsigned long long r;
    asm("mov.b64 %0, {%1, %2};" : "=l"(r) : "f"(lo), "f"(hi));
    return r;
}
__device__ __forceinline__ float2 unpack_f32x2(unsigned long long v) {
    float2 r;
    asm("mov.b64 {%0, %1}, %2;" : "=f"(r.x), "=f"(r.y) : "l"(v));
    return r;
}

// ---------------- K0: zero counts ----------------
__global__ void zero_counts_kernel() {
    int i = blockIdx.x * blockDim.x + threadIdx.x;
    if (i < NUM_EDGES) g_counts[i] = 0;
}

// ---------------- K1: histogram of edge ids (hyperedge_index is int32) ----------------
__global__ void count_kernel(const int* __restrict__ he) {
    int c = blockIdx.x * blockDim.x + threadIdx.x;
    if (c < NUM_CONN) {
        int e = he[NUM_CONN + c];
        if ((unsigned)e < NUM_EDGES) atomicAdd(&g_counts[e], 1);
    }
}

// ---------------- K2a: per-block reduce of counts ----------------
__global__ void __launch_bounds__(SCAN_BLK) scan_reduce_kernel() {
    __shared__ int ws[SCAN_BLK / 32];
    int i = blockIdx.x * SCAN_BLK + threadIdx.x;
    int v = (i < NUM_EDGES) ? g_counts[i] : 0;
    int lane = threadIdx.x & 31, wid = threadIdx.x >> 5;
    #pragma unroll
    for (int o = 16; o; o >>= 1) v += __shfl_xor_sync(0xffffffffu, v, o);
    if (lane == 0) ws[wid] = v;
    __syncthreads();
    if (threadIdx.x < SCAN_BLK / 32) {
        int s = ws[threadIdx.x];
        #pragma unroll
        for (int o = SCAN_BLK / 64; o; o >>= 1) s += __shfl_xor_sync(0xffffffffu, s, o);
        if (threadIdx.x == 0) g_partials[blockIdx.x] = s;
    }
}

// ---------------- K2b: scan the 196 partials (one block) ----------------
__global__ void __launch_bounds__(256) scan_partials_kernel() {
    __shared__ int ws[8];
    int tid = threadIdx.x, lane = tid & 31, wid = tid >> 5;
    int v = (tid < SCAN_NBLK) ? g_partials[tid] : 0;
    int x = v;
    #pragma unroll
    for (int off = 1; off < 32; off <<= 1) {
        int t = __shfl_up_sync(0xffffffffu, x, off);
        if (lane >= off) x += t;
    }
    if (lane == 31) ws[wid] = x;
    __syncthreads();
    if (wid == 0 && lane < 8) {
        int t = ws[lane];
        int y = t;
        #pragma unroll
        for (int off = 1; off < 8; off <<= 1) {
            int u = __shfl_up_sync(0xffu, y, off);
            if (lane >= off) y += u;
        }
        ws[lane] = y - t;
    }
    __syncthreads();
    int excl = (x - v) + ws[wid];
    if (tid < SCAN_NBLK) g_partials[tid] = excl;
    if (tid == SCAN_NBLK - 1) g_offsets[NUM_EDGES] = excl + v;  // grand total
}

// ---------------- K2c: per-block scan + add partial prefix ----------------
__global__ void __launch_bounds__(SCAN_BLK) scan_write_kernel() {
    __shared__ int ws[SCAN_BLK / 32];
    int i = blockIdx.x * SCAN_BLK + threadIdx.x;
    int lane = threadIdx.x & 31, wid = threadIdx.x >> 5;
    int v = (i < NUM_EDGES) ? g_counts[i] : 0;
    int x = v;
    #pragma unroll
    for (int off = 1; off < 32; off <<= 1) {
        int t = __shfl_up_sync(0xffffffffu, x, off);
        if (lane >= off) x += t;
    }
    if (lane == 31) ws[wid] = x;
    __syncthreads();
    if (wid == 0 && lane < SCAN_BLK / 32) {
        int t = ws[lane];
        int y = t;
        #pragma unroll
        for (int off = 1; off < SCAN_BLK / 32; off <<= 1) {
            int u = __shfl_up_sync(0xffu, y, off);
            if (lane >= off) y += u;
        }
        ws[lane] = y - t;
    }
    __syncthreads();
    int excl = (x - v) + ws[wid] + g_partials[blockIdx.x];
    if (i < NUM_EDGES) {
        g_offsets[i] = excl;
        g_cursor[i]  = excl;
    }
}

// ---------------- K3: fill CSR ----------------
__global__ void fill_kernel(const int* __restrict__ he) {
    int c = blockIdx.x * blockDim.x + threadIdx.x;
    if (c < NUM_CONN) {
        int e = he[NUM_CONN + c];
        if ((unsigned)e < NUM_EDGES) {
            int pos = atomicAdd(&g_cursor[e], 1);
            int n = he[c];
            g_csr[pos] = ((unsigned)n < NUM_NODES) ? n : 0;
        }
    }
}

// ---------------- K4: FUSED gather-mean + GEMM1(FFMA2) + LN + ReLU + GEMM2 ----------------
#define ROWS 25
__global__ void __launch_bounds__(128) fused_mlp_kernel(
    const float* __restrict__ nf,
    const float* __restrict__ W1, const float* __restrict__ b1,
    const float* __restrict__ lng, const float* __restrict__ lnb,
    const float* __restrict__ W2, const float* __restrict__ b2,
    float* __restrict__ out)
{
    __shared__ float Xs[ROWS][IN_DIM];       // 25.6 KB
    __shared__ float Hs[ROWS][HIDDEN];       // 12.8 KB
    __shared__ float W2s[HIDDEN * OUT_DIM];  // 8.7 KB
    __shared__ float b2s[OUT_DIM];

    int tid  = threadIdx.x;
    int wid  = tid >> 5, lane = tid & 31;
    int row0 = blockIdx.x * ROWS;

    for (int idx = tid; idx < HIDDEN * OUT_DIM; idx += 128) W2s[idx] = W2[idx];
    if (tid < OUT_DIM) b2s[tid] = b2[tid];

    // ---- gather + mean straight into Xs (warp-per-edge, 2-way unrolled) ----
    for (int r = wid; r < ROWS; r += 4) {
        int e   = row0 + r;
        int beg = g_offsets[e];
        int end = g_offsets[e + 1];
        float4 a0 = make_float4(0.f, 0.f, 0.f, 0.f);
        float4 a1 = make_float4(0.f, 0.f, 0.f, 0.f);
        int i = beg;
        for (; i + 2 <= end; i += 2) {
            int n0 = g_csr[i];
            int n1 = g_csr[i + 1];
            const float4* r0 = (const float4*)(nf + (size_t)n0 * IN_DIM);
            const float4* r1 = (const float4*)(nf + (size_t)n1 * IN_DIM);
            float4 u0 = __ldg(&r0[lane]);
            float4 u1 = __ldg(&r0[32 + lane]);
            float4 v0 = __ldg(&r1[lane]);
            float4 v1 = __ldg(&r1[32 + lane]);
            a0.x += u0.x; a0.y += u0.y; a0.z += u0.z; a0.w += u0.w;
            a1.x += u1.x; a1.y += u1.y; a1.z += u1.z; a1.w += u1.w;
            a0.x += v0.x; a0.y += v0.y; a0.z += v0.z; a0.w += v0.w;
            a1.x += v1.x; a1.y += v1.y; a1.z += v1.z; a1.w += v1.w;
        }
        if (i < end) {
            int n = g_csr[i];
            const float4* row = (const float4*)(nf + (size_t)n * IN_DIM);
            float4 v0 = __ldg(&row[lane]);
            float4 v1 = __ldg(&row[32 + lane]);
            a0.x += v0.x; a0.y += v0.y; a0.z += v0.z; a0.w += v0.w;
            a1.x += v1.x; a1.y += v1.y; a1.z += v1.z; a1.w += v1.w;
        }
        int cnt = end - beg;
        float inv = 1.f / (float)(cnt > 0 ? cnt : 1);
        a0.x *= inv; a0.y *= inv; a0.z *= inv; a0.w *= inv;
        a1.x *= inv; a1.y *= inv; a1.z *= inv; a1.w *= inv;
        ((float4*)&Xs[r][0])[lane]      = a0;
        ((float4*)&Xs[r][0])[32 + lane] = a1;
    }
    __syncthreads();

    // ---- GEMM1, packed f32x2, software-pipelined W1 loads ----
    unsigned long long acc2[ROWS];
    #pragma unroll
    for (int r = 0; r < ROWS; r++) acc2[r] = 0ULL;

    float w0 = __ldg(&W1[0 * HIDDEN + tid]);
    float w1 = __ldg(&W1[1 * HIDDEN + tid]);
    float w2 = __ldg(&W1[2 * HIDDEN + tid]);
    float w3 = __ldg(&W1[3 * HIDDEN + tid]);

    #pragma unroll 2
    for (int k = 0; k < IN_DIM - 4; k += 4) {
        float n0 = __ldg(&W1[(k + 4) * HIDDEN + tid]);
        float n1 = __ldg(&W1[(k + 5) * HIDDEN + tid]);
        float n2 = __ldg(&W1[(k + 6) * HIDDEN + tid]);
        float n3 = __ldg(&W1[(k + 7) * HIDDEN + tid]);
        unsigned long long wA = pack_f32x2(w0, w1);
        unsigned long long wB = pack_f32x2(w2, w3);
        #pragma unroll
        for (int r = 0; r < ROWS; r++) {
            ulonglong2 xx = *(const ulonglong2*)&Xs[r][k];  // LDS.128 broadcast
            fma_f32x2(acc2[r], xx.x, wA);
            fma_f32x2(acc2[r], xx.y, wB);
        }
        w0 = n0; w1 = n1; w2 = n2; w3 = n3;
    }
    {   // last quad
        unsigned long long wA = pack_f32x2(w0, w1);
        unsigned long long wB = pack_f32x2(w2, w3);
        #pragma unroll
        for (int r = 0; r < ROWS; r++) {
            ulonglong2 xx = *(const ulonglong2*)&Xs[r][IN_DIM - 4];
            fma_f32x2(acc2[r], xx.x, wA);
            fma_f32x2(acc2[r], xx.y, wB);
        }
    }

    float b1v = b1[tid];
    #pragma unroll
    for (int r = 0; r < ROWS; r++) {
        float2 p = unpack_f32x2(acc2[r]);
        Hs[r][tid] = p.x + p.y + b1v;
    }
    __syncthreads();

    // ---- LayerNorm + ReLU, warp-per-row ----
    for (int r = wid; r < ROWS; r += 4) {
        float s = 0.f, s2 = 0.f;
        #pragma unroll
        for (int j = 0; j < 4; j++) {
            float v = Hs[r][lane + 32 * j];
            s += v; s2 += v * v;
        }
        #pragma unroll
        for (int o = 16; o; o >>= 1) {
            s  += __shfl_xor_sync(0xffffffffu, s, o);
            s2 += __shfl_xor_sync(0xffffffffu, s2, o);
        }
        float mu  = s * (1.f / HIDDEN);
        float var = s2 * (1.f / HIDDEN) - mu * mu;
        float rs  = rsqrtf(var + LN_EPS);
        #pragma unroll
        for (int j = 0; j < 4; j++) {
            int c = lane + 32 * j;
            float v = (Hs[r][c] - mu) * rs * lng[c] + lnb[c];
            Hs[r][c] = fmaxf(v, 0.f);
        }
    }
    __syncthreads();

    // ---- GEMM2 ----
    for (int idx = tid; idx < ROWS * OUT_DIM; idx += 128) {
        int r = idx / OUT_DIM, o = idx % OUT_DIM;
        float s = b2s[o];
        #pragma unroll 8
        for (int j = 0; j < HIDDEN; j++) s = fmaf(Hs[r][j], W2s[j * OUT_DIM + o], s);
        out[(size_t)(row0 + r) * OUT_DIM + o] = s;
    }
}

// ---------------- launch ----------------
extern "C" void kernel_launch(void* const* d_in, const int* in_sizes, int n_in,
                              void* d_out, int out_size)
{
    const float* node_features = (const float*)d_in[0];
    const int*   he            = (const int*)d_in[1];   // int32 (JAX x64 disabled)
    const float* W1            = (const float*)d_in[2];
    const float* b1            = (const float*)d_in[3];
    const float* ln_g          = (const float*)d_in[4];
    const float* ln_b          = (const float*)d_in[5];
    const float* W2            = (const float*)d_in[6];
    const float* b2            = (const float*)d_in[7];
    float*       out           = (float*)d_out;

    zero_counts_kernel<<<(NUM_EDGES + 255) / 256, 256>>>();
    count_kernel<<<(NUM_CONN + 255) / 256, 256>>>(he);
    scan_reduce_kernel<<<SCAN_NBLK, SCAN_BLK>>>();
    scan_partials_kernel<<<1, 256>>>();
    scan_write_kernel<<<SCAN_NBLK, SCAN_BLK>>>();
    fill_kernel<<<(NUM_CONN + 255) / 256, 256>>>(he);
    fused_mlp_kernel<<<NUM_EDGES / ROWS, 128>>>(node_features,
                                                W1, b1, ln_g, ln_b, W2, b2, out);
}